// round 9
// baseline (speedup 1.0000x reference)
#include <cuda_runtime.h>
#include <cuda_fp16.h>
#include <cstdint>

// ---------------------------------------------------------------------------
// GCN_8796093022507: 2-layer GCN, dropout 0.6, N=100000, E=6.4M.
// R9: R5 skeleton (best, 119.5us) minus critical-path overhead:
//  - threefry split keys computed on HOST, passed as args (k_init removed)
//  - g_deg zeroed by cudaMemsetAsync graph node; acc zeroing folded into nodes
//  - dropout threefry (h0 + 16-bit dropout2 keep masks) generated by EXTRA
//    blocks of the deg kernel -> ALU overlaps the REDG-bound histogram
//  - edge passes: unchanged R5 config (2 edges/thread, 256 thr, skip-zero L0)
// PRNG: JAX threefry2x32, partitionable (verified).
// ---------------------------------------------------------------------------

#define NMAX 100000

__device__ float    g_dinv[NMAX];
__device__ float    g_h0[NMAX];     // dropout1(x) (pre-dinv)
__device__ int      g_deg[NMAX];
__device__ unsigned short g_mask16[NMAX];  // dropout2 keep bits, 16 per node
__device__ __align__(16) __half g_u[NMAX];  // layer1 payload: h0*dinv
__device__ __align__(16) __half g_w[NMAX];  // layer2 payload: t*dinv
__device__ float    g_acc1[NMAX];
__device__ float    g_acc2[NMAX];

#define TF_BODY                                                          \
  unsigned k2 = k0 ^ k1 ^ 0x1BD11BDAu;                                   \
  x0 += k0; x1 += k1;                                                    \
  TFR(13) TFR(15) TFR(26) TFR(6)                                         \
  x0 += k1; x1 += k2 + 1u;                                               \
  TFR(17) TFR(29) TFR(16) TFR(24)                                        \
  x0 += k2; x1 += k0 + 2u;                                               \
  TFR(13) TFR(15) TFR(26) TFR(6)                                         \
  x0 += k0; x1 += k1 + 3u;                                               \
  TFR(17) TFR(29) TFR(16) TFR(24)                                        \
  x0 += k1; x1 += k2 + 4u;                                               \
  TFR(13) TFR(15) TFR(26) TFR(6)                                         \
  x0 += k2; x1 += k0 + 5u;

__device__ __forceinline__ uint2 tf2x32(unsigned k0, unsigned k1,
                                        unsigned x0, unsigned x1) {
#define TFR(r) { x0 += x1; x1 = (x1 << (r)) | (x1 >> (32 - (r))); x1 ^= x0; }
  TF_BODY
#undef TFR
  return make_uint2(x0, x1);
}

static void tf2x32_host(unsigned k0, unsigned k1, unsigned x0, unsigned x1,
                        unsigned* o0, unsigned* o1) {
#define TFR(r) { x0 += x1; x1 = (x1 << (r)) | (x1 >> (32 - (r))); x1 ^= x0; }
  TF_BODY
#undef TFR
  *o0 = x0; *o1 = x1;
}

__device__ __forceinline__ bool keep40(unsigned k0, unsigned k1, unsigned i) {
  uint2 z = tf2x32(k0, k1, 0u, i);
  unsigned bits = z.x ^ z.y;
  float u = __uint_as_float((bits >> 9) | 0x3F800000u) - 1.0f;
  return u < 0.4f;
}

// Uniform per-thread dtype check: 4 int64 words all in [0,N) => int64 input.
__device__ __forceinline__ bool detect64(const void* ei, int N) {
  const longlong2* p = (const longlong2*)ei;
  longlong2 a = __ldg(&p[0]);
  longlong2 b = __ldg(&p[1]);
  return ((unsigned long long)a.x < (unsigned long long)N) &
         ((unsigned long long)a.y < (unsigned long long)N) &
         ((unsigned long long)b.x < (unsigned long long)N) &
         ((unsigned long long)b.y < (unsigned long long)N);
}

// Blocks [0, nblkQ): in-degree histogram (4 edges/thread, int4).
// Blocks [nblkQ, ...): dropout mask generation (overlaps the REDG-bound part).
__global__ void k_deg_mask(const void* ei, const float* __restrict__ x,
                           int nquads, int E, int N, int nblkQ,
                           unsigned k10, unsigned k11,
                           unsigned k20, unsigned k21) {
  if (blockIdx.x < nblkQ) {
    int i = blockIdx.x * blockDim.x + threadIdx.x;
    if (i >= nquads) return;
    int e0 = 4 * i;
    if (detect64(ei, N)) {
      const long long* dstr = (const long long*)ei + E;
      for (int k = 0; k < 4 && e0 + k < E; k++) {
        int d = (int)dstr[e0 + k];
        if ((unsigned)d < (unsigned)N) atomicAdd(&g_deg[d], 1);
      }
    } else {
      const int* dstr = (const int*)ei + E;
      if (e0 + 3 < E) {
        int4 d4 = ((const int4*)dstr)[i];
        atomicAdd(&g_deg[d4.x], 1);
        atomicAdd(&g_deg[d4.y], 1);
        atomicAdd(&g_deg[d4.z], 1);
        atomicAdd(&g_deg[d4.w], 1);
      } else {
        for (int k = 0; k < 4 && e0 + k < E; k++)
          atomicAdd(&g_deg[dstr[e0 + k]], 1);
      }
    }
  } else {
    // dropout2 keep-mask gen: one thread per (n, j), 16 threads per node.
    int gid = (blockIdx.x - nblkQ) * blockDim.x + threadIdx.x;
    int n = gid >> 4, j = gid & 15;
    if (n >= N) return;
    bool keep = keep40(k20, k21, (unsigned)gid);     // flat (N,16) index
    unsigned bal = __ballot_sync(0xFFFFFFFFu, keep);
    int lane = threadIdx.x & 31;
    if (lane == 0)  g_mask16[n]     = (unsigned short)(bal & 0xFFFFu);
    if (lane == 16) g_mask16[n]     = (unsigned short)(bal >> 16);
    // dropout1 on x (one hash per node), done by lane j==1 of each node group
    if (j == 1)
      g_h0[n] = keep40(k10, k11, (unsigned)n) ? x[n] * 2.5f : 0.0f;
  }
}

__global__ void k_node1(int N) {
  int i = blockIdx.x * blockDim.x + threadIdx.x;
  if (i >= N) return;
  g_acc1[i] = 0.0f;
  int d = g_deg[i];
  float dinv = (d > 0) ? rsqrtf((float)d) : 0.0f;
  g_dinv[i] = dinv;
  g_u[i] = __float2half(g_h0[i] * dinv);
}

// Scatter payload[src] into acc[dst]; 2 edges/thread (proven-best config).
// SKIPZ=1: skip zero payloads (layer1, ~60% dead). SKIPZ=0: always atomic.
template <int LAYER, int SKIPZ>
__global__ void __launch_bounds__(256) k_edge(const void* ei, int npairs, int E, int N) {
  int i = blockIdx.x * blockDim.x + threadIdx.x;
  if (i >= npairs) return;
  const __half* tab = (LAYER == 0) ? g_u : g_w;
  float* acc = (LAYER == 0) ? g_acc1 : g_acc2;
  int e0 = 2 * i;
  if (!detect64(ei, N)) {
    const int* p = (const int*)ei;
    if (e0 + 1 < E) {
      int2 sv = ((const int2*)p)[i];
      int2 dv = ((const int2*)(p + E))[i];
      unsigned short b0 = __ldg((const unsigned short*)&tab[sv.x]);
      unsigned short b1 = __ldg((const unsigned short*)&tab[sv.y]);
      if (!SKIPZ || b0) atomicAdd(&acc[dv.x], __half2float(__ushort_as_half(b0)));
      if (!SKIPZ || b1) atomicAdd(&acc[dv.y], __half2float(__ushort_as_half(b1)));
    } else {
      int s = p[e0], d = p[E + e0];
      unsigned short b = __ldg((const unsigned short*)&tab[s]);
      if (!SKIPZ || b) atomicAdd(&acc[d], __half2float(__ushort_as_half(b)));
    }
  } else {
    const long long* p = (const long long*)ei;
    for (int k = 0; k < 2 && e0 + k < E; k++) {
      int s = (int)p[e0 + k], d = (int)p[E + e0 + k];
      float v = __half2float(tab[s]);
      if (v != 0.0f) atomicAdd(&acc[d], v);
    }
  }
}

__global__ void k_node2(const float* __restrict__ W1, const float* __restrict__ b1,
                        const float* __restrict__ W2, int N) {
  int tid = blockIdx.x * blockDim.x + threadIdx.x;
  int n = tid >> 4, j = tid & 15;
  if (n >= N) return;
  float dinv = g_dinv[n];
  float s1 = g_acc1[n] * dinv;                                 // finish layer1
  float v = fmaxf(s1 * __ldg(&W1[j]) + __ldg(&b1[j]), 0.0f);   // relu
  v = ((g_mask16[n] >> j) & 1) ? v * 2.5f : 0.0f;              // dropout2 (mask)
  v *= __ldg(&W2[j]);
  #pragma unroll
  for (int off = 8; off; off >>= 1)
    v += __shfl_xor_sync(0xFFFFFFFFu, v, off, 16);
  if (j == 0) {
    g_w[n] = __float2half(v * dinv);                           // payload = t*dinv
    g_acc2[n] = 0.0f;
  }
}

__global__ void k_node3(const float* __restrict__ b2, float* __restrict__ out, int N) {
  int i = blockIdx.x * blockDim.x + threadIdx.x;
  if (i >= N) return;
  out[i] = g_acc2[i] * g_dinv[i] + b2[0];
}

extern "C" void kernel_launch(void* const* d_in, const int* in_sizes, int n_in,
                              void* d_out, int out_size) {
  const void*  ei = d_in[1];
  const float* x  = (const float*)d_in[0];
  const float* W1 = (const float*)d_in[2];
  const float* b1 = (const float*)d_in[3];
  const float* W2 = (const float*)d_in[4];
  const float* b2 = (const float*)d_in[5];
  float* out = (float*)d_out;

  int N = in_sizes[0];
  int E = in_sizes[1] / 2;

  // Host-side threefry: jax.random.key(42), partitionable split(2).
  unsigned k10, k11, k20, k21;
  tf2x32_host(0u, 42u, 0u, 0u, &k10, &k11);
  tf2x32_host(0u, 42u, 0u, 1u, &k20, &k21);

  static void* p_deg = nullptr;
  if (!p_deg) cudaGetSymbolAddress(&p_deg, g_deg);

  const int TB = 256;
  int nblkN   = (N + TB - 1) / TB;
  int npairs  = (E + 1) / 2;
  int nquads  = (E + 3) / 4;
  int nblkP   = (npairs + TB - 1) / TB;
  int nblkQ   = (nquads + TB - 1) / TB;
  int nblkN16 = (N * 16 + TB - 1) / TB;

  cudaMemsetAsync(p_deg, 0, (size_t)N * sizeof(int));
  k_deg_mask<<<nblkQ + nblkN16, TB>>>(ei, x, nquads, E, N, nblkQ,
                                      k10, k11, k20, k21);
  k_node1     <<<nblkN,  TB>>>(N);
  k_edge<0,1> <<<nblkP,  TB>>>(ei, npairs, E, N);
  k_node2     <<<nblkN16, TB>>>(W1, b1, W2, N);
  k_edge<1,0> <<<nblkP,  TB>>>(ei, npairs, E, N);
  k_node3     <<<nblkN,  TB>>>(b2, out, N);
}

// round 10
// speedup vs baseline: 1.0166x; 1.0166x over previous
#include <cuda_runtime.h>
#include <cuda_fp16.h>
#include <cstdint>

// ---------------------------------------------------------------------------
// GCN_8796093022507: 2-layer GCN, dropout 0.6, N=100000, E=6.4M.
// R10: R9 minus node2's shfl reduction: node2 is now 1 thread/node with a
// 16-channel register loop (s1 is scalar -> t = 2.5*sum_{j in mask} W2j*relu(..)).
// Scatter passes at REDG floor (R5-R9 evidence); edge configs: proven-best
// (layer0: ushort zero-skip; layer1: no test).
// PRNG: threefry partitionable, host-derived split keys (verified).
// ---------------------------------------------------------------------------

#define NMAX 100000

__device__ float    g_dinv[NMAX];
__device__ float    g_h0[NMAX];            // dropout1(x) (pre-dinv)
__device__ int      g_deg[NMAX];
__device__ unsigned short g_mask16[NMAX];  // dropout2 keep bits, 16 per node
__device__ __align__(16) __half g_u[NMAX]; // layer1 payload: h0*dinv
__device__ __align__(16) __half g_w[NMAX]; // layer2 payload: t*dinv
__device__ float    g_acc1[NMAX];
__device__ float    g_acc2[NMAX];

#define TF_BODY                                                          \
  unsigned k2 = k0 ^ k1 ^ 0x1BD11BDAu;                                   \
  x0 += k0; x1 += k1;                                                    \
  TFR(13) TFR(15) TFR(26) TFR(6)                                         \
  x0 += k1; x1 += k2 + 1u;                                               \
  TFR(17) TFR(29) TFR(16) TFR(24)                                        \
  x0 += k2; x1 += k0 + 2u;                                               \
  TFR(13) TFR(15) TFR(26) TFR(6)                                         \
  x0 += k0; x1 += k1 + 3u;                                               \
  TFR(17) TFR(29) TFR(16) TFR(24)                                        \
  x0 += k1; x1 += k2 + 4u;                                               \
  TFR(13) TFR(15) TFR(26) TFR(6)                                         \
  x0 += k2; x1 += k0 + 5u;

__device__ __forceinline__ uint2 tf2x32(unsigned k0, unsigned k1,
                                        unsigned x0, unsigned x1) {
#define TFR(r) { x0 += x1; x1 = (x1 << (r)) | (x1 >> (32 - (r))); x1 ^= x0; }
  TF_BODY
#undef TFR
  return make_uint2(x0, x1);
}

static void tf2x32_host(unsigned k0, unsigned k1, unsigned x0, unsigned x1,
                        unsigned* o0, unsigned* o1) {
#define TFR(r) { x0 += x1; x1 = (x1 << (r)) | (x1 >> (32 - (r))); x1 ^= x0; }
  TF_BODY
#undef TFR
  *o0 = x0; *o1 = x1;
}

__device__ __forceinline__ bool keep40(unsigned k0, unsigned k1, unsigned i) {
  uint2 z = tf2x32(k0, k1, 0u, i);
  unsigned bits = z.x ^ z.y;
  float u = __uint_as_float((bits >> 9) | 0x3F800000u) - 1.0f;
  return u < 0.4f;
}

// Uniform dtype check: first 4 int64 words all in [0,N) => int64 input.
__device__ __forceinline__ bool detect64(const void* ei, int N) {
  const longlong2* p = (const longlong2*)ei;
  longlong2 a = __ldg(&p[0]);
  longlong2 b = __ldg(&p[1]);
  return ((unsigned long long)a.x < (unsigned long long)N) &
         ((unsigned long long)a.y < (unsigned long long)N) &
         ((unsigned long long)b.x < (unsigned long long)N) &
         ((unsigned long long)b.y < (unsigned long long)N);
}

// Blocks [0, nblkQ): in-degree histogram (4 edges/thread, int4).
// Blocks [nblkQ, ...): dropout1 h0 + dropout2 keep-mask gen (ALU overlaps REDG).
__global__ void k_deg_mask(const void* ei, const float* __restrict__ x,
                           int nquads, int E, int N, int nblkQ,
                           unsigned k10, unsigned k11,
                           unsigned k20, unsigned k21) {
  if (blockIdx.x < nblkQ) {
    int i = blockIdx.x * blockDim.x + threadIdx.x;
    if (i >= nquads) return;
    int e0 = 4 * i;
    if (detect64(ei, N)) {
      const long long* dstr = (const long long*)ei + E;
      for (int k = 0; k < 4 && e0 + k < E; k++) {
        int d = (int)dstr[e0 + k];
        if ((unsigned)d < (unsigned)N) atomicAdd(&g_deg[d], 1);
      }
    } else {
      const int* dstr = (const int*)ei + E;
      if (e0 + 3 < E) {
        int4 d4 = ((const int4*)dstr)[i];
        atomicAdd(&g_deg[d4.x], 1);
        atomicAdd(&g_deg[d4.y], 1);
        atomicAdd(&g_deg[d4.z], 1);
        atomicAdd(&g_deg[d4.w], 1);
      } else {
        for (int k = 0; k < 4 && e0 + k < E; k++)
          atomicAdd(&g_deg[dstr[e0 + k]], 1);
      }
    }
  } else {
    int gid = (blockIdx.x - nblkQ) * blockDim.x + threadIdx.x;
    int n = gid >> 4, j = gid & 15;
    if (n >= N) return;
    bool keep = keep40(k20, k21, (unsigned)gid);    // flat (N,16) index
    unsigned bal = __ballot_sync(0xFFFFFFFFu, keep);
    int lane = threadIdx.x & 31;
    if (lane == 0)  g_mask16[n] = (unsigned short)(bal & 0xFFFFu);
    if (lane == 16) g_mask16[n] = (unsigned short)(bal >> 16);
    if (j == 1)
      g_h0[n] = keep40(k10, k11, (unsigned)n) ? x[n] * 2.5f : 0.0f;
  }
}

__global__ void k_node1(int N) {
  int i = blockIdx.x * blockDim.x + threadIdx.x;
  if (i >= N) return;
  g_acc1[i] = 0.0f;
  int d = g_deg[i];
  float dinv = (d > 0) ? rsqrtf((float)d) : 0.0f;
  g_dinv[i] = dinv;
  g_u[i] = __float2half(g_h0[i] * dinv);
}

// Scatter payload[src] into acc[dst]; 2 edges/thread.
// SKIPZ=1: skip zero payloads (layer1, ~60% dead). SKIPZ=0: always atomic.
template <int LAYER, int SKIPZ>
__global__ void __launch_bounds__(256) k_edge(const void* ei, int npairs, int E, int N) {
  int i = blockIdx.x * blockDim.x + threadIdx.x;
  if (i >= npairs) return;
  const __half* tab = (LAYER == 0) ? g_u : g_w;
  float* acc = (LAYER == 0) ? g_acc1 : g_acc2;
  int e0 = 2 * i;
  if (!detect64(ei, N)) {
    const int* p = (const int*)ei;
    if (e0 + 1 < E) {
      int2 sv = ((const int2*)p)[i];
      int2 dv = ((const int2*)(p + E))[i];
      unsigned short b0 = __ldg((const unsigned short*)&tab[sv.x]);
      unsigned short b1 = __ldg((const unsigned short*)&tab[sv.y]);
      if (!SKIPZ || b0) atomicAdd(&acc[dv.x], __half2float(__ushort_as_half(b0)));
      if (!SKIPZ || b1) atomicAdd(&acc[dv.y], __half2float(__ushort_as_half(b1)));
    } else {
      int s = p[e0], d = p[E + e0];
      unsigned short b = __ldg((const unsigned short*)&tab[s]);
      if (!SKIPZ || b) atomicAdd(&acc[d], __half2float(__ushort_as_half(b)));
    }
  } else {
    const long long* p = (const long long*)ei;
    for (int k = 0; k < 2 && e0 + k < E; k++) {
      int s = (int)p[e0 + k], d = (int)p[E + e0 + k];
      float v = __half2float(tab[s]);
      if (v != 0.0f) atomicAdd(&acc[d], v);
    }
  }
}

// 1 thread/node: t = 2.5 * sum_{j in mask} W2j * relu(W1j*s1 + b1j); no shfl.
__global__ void k_node2(const float* __restrict__ W1, const float* __restrict__ b1,
                        const float* __restrict__ W2, int N) {
  int n = blockIdx.x * blockDim.x + threadIdx.x;
  if (n >= N) return;
  float dinv = g_dinv[n];
  float s1 = g_acc1[n] * dinv;                       // finish layer1
  unsigned m = g_mask16[n];
  float t = 0.0f;
  #pragma unroll
  for (int j = 0; j < 16; j++) {
    float v = fmaxf(s1 * __ldg(&W1[j]) + __ldg(&b1[j]), 0.0f);   // relu
    if ((m >> j) & 1u) t = fmaf(v, __ldg(&W2[j]), t);            // dropout2+dot
  }
  g_w[n] = __float2half(t * 2.5f * dinv);            // payload = t*dinv
  g_acc2[n] = 0.0f;
}

__global__ void k_node3(const float* __restrict__ b2, float* __restrict__ out, int N) {
  int i = blockIdx.x * blockDim.x + threadIdx.x;
  if (i >= N) return;
  out[i] = g_acc2[i] * g_dinv[i] + b2[0];
}

extern "C" void kernel_launch(void* const* d_in, const int* in_sizes, int n_in,
                              void* d_out, int out_size) {
  const float* x  = (const float*)d_in[0];
  const void*  ei = d_in[1];
  const float* W1 = (const float*)d_in[2];
  const float* b1 = (const float*)d_in[3];
  const float* W2 = (const float*)d_in[4];
  const float* b2 = (const float*)d_in[5];
  float* out = (float*)d_out;

  int N = in_sizes[0];
  int E = in_sizes[1] / 2;

  // Host-side threefry: jax.random.key(42), partitionable split(2).
  unsigned k10, k11, k20, k21;
  tf2x32_host(0u, 42u, 0u, 0u, &k10, &k11);
  tf2x32_host(0u, 42u, 0u, 1u, &k20, &k21);

  static void* p_deg = nullptr;
  if (!p_deg) cudaGetSymbolAddress(&p_deg, g_deg);

  const int TB = 256;
  int nblkN   = (N + TB - 1) / TB;
  int npairs  = (E + 1) / 2;
  int nquads  = (E + 3) / 4;
  int nblkP   = (npairs + TB - 1) / TB;
  int nblkQ   = (nquads + TB - 1) / TB;
  int nblkN16 = (N * 16 + TB - 1) / TB;

  cudaMemsetAsync(p_deg, 0, (size_t)N * sizeof(int));
  k_deg_mask  <<<nblkQ + nblkN16, TB>>>(ei, x, nquads, E, N, nblkQ,
                                        k10, k11, k20, k21);
  k_node1     <<<nblkN,  TB>>>(N);
  k_edge<0,1> <<<nblkP,  TB>>>(ei, npairs, E, N);
  k_node2     <<<nblkN,  TB>>>(W1, b1, W2, N);
  k_edge<1,0> <<<nblkP,  TB>>>(ei, npairs, E, N);
  k_node3     <<<nblkN,  TB>>>(b2, out, N);
}